// round 7
// baseline (speedup 1.0000x reference)
#include <cuda_runtime.h>

// WENO-Z 1-D periodic, B=16 x N=2^20 fp32.
// Persistent grid-stride CTAs + one-deep LDG prefetch: next tile's loads are
// in flight while the current tile's packed-f32x2 WENO math executes.
// VEC=8 (best op count per element, R5 algebra).

#define N_ELEMS   1048576
#define N_MASK    (N_ELEMS - 1)
#define TPB       128
#define VEC       8
#define TILE      (TPB * VEC)                 // 1024
#define NTILES    ((16 * N_ELEMS) / TILE)     // 16384
#define NBLOCKS   (148 * 8)                   // one resident wave

#define EPS 1e-13f

typedef unsigned long long u64;

__device__ __forceinline__ u64 pk(float lo, float hi) {
    u64 r; asm("mov.b64 %0, {%1, %2};" : "=l"(r) : "f"(lo), "f"(hi)); return r;
}
__device__ __forceinline__ void upk(float& lo, float& hi, u64 v) {
    asm("mov.b64 {%0, %1}, %2;" : "=f"(lo), "=f"(hi) : "l"(v));
}
__device__ __forceinline__ float hif(u64 v) { float lo, hi; upk(lo, hi, v); return hi; }
__device__ __forceinline__ u64 shifted(u64 a, u64 b) {   // (hi(a), lo(b))
    float alo, ahi, blo, bhi; upk(alo, ahi, a); upk(blo, bhi, b); return pk(ahi, blo);
}
__device__ __forceinline__ u64 f2mul(u64 a, u64 b) {
    u64 d; asm("mul.rn.f32x2 %0, %1, %2;" : "=l"(d) : "l"(a), "l"(b)); return d;
}
__device__ __forceinline__ u64 f2add(u64 a, u64 b) {
    u64 d; asm("add.rn.f32x2 %0, %1, %2;" : "=l"(d) : "l"(a), "l"(b)); return d;
}
__device__ __forceinline__ u64 f2fma(u64 a, u64 b, u64 c) {
    u64 d; asm("fma.rn.f32x2 %0, %1, %2, %3;" : "=l"(d) : "l"(a), "l"(b), "l"(c)); return d;
}
__device__ __forceinline__ u64 f2abs(u64 a) { return a & 0x7FFFFFFF7FFFFFFFULL; }

// Load the 13-float stencil window for `tile` (thread-local, aligned LDG.128).
__device__ __forceinline__ void load_win(const float* __restrict__ x, int tile, int t,
                                         float4& g0, float4& g1, float4& g2, float& g3)
{
    const int bb    = tile >> 10;                 // batch = tile / (N/TILE)
    const int start = (tile & 1023) * TILE;
    const float* xb = x + ((size_t)bb << 20);
    const int base  = start + t * VEC - 4;        // multiple of 4 -> 16B aligned
    g0 = *reinterpret_cast<const float4*>(xb + ((base)      & N_MASK));
    g1 = *reinterpret_cast<const float4*>(xb + ((base + 4)  & N_MASK));
    g2 = *reinterpret_cast<const float4*>(xb + ((base + 8)  & N_MASK));
    g3 = xb[(base + 12) & N_MASK];
}

__global__ void __launch_bounds__(TPB, 8) weno_z_kernel(
    const float* __restrict__ x, float* __restrict__ out)
{
    const int t = threadIdx.x;

    const u64 Cm1  = pk(-1.0f, -1.0f);
    const u64 C2   = pk(2.0f, 2.0f);
    const u64 C3   = pk(3.0f, 3.0f);
    const u64 C43  = pk(4.0f/3.0f, 4.0f/3.0f);
    const u64 C05  = pk(0.5f, 0.5f);
    const u64 Cm05 = pk(-0.5f, -0.5f);
    const u64 C13  = pk(1.0f/3.0f, 1.0f/3.0f);
    const u64 Cm16 = pk(-1.0f/6.0f, -1.0f/6.0f);
    const u64 Ceps = pk(EPS, EPS);
    const u64 Cd0  = pk(0.1f, 0.1f);
    const u64 Cd1  = pk(0.6f, 0.6f);
    const u64 Cd2  = pk(0.3f, 0.3f);

    int tile = blockIdx.x;
    float4 c0, c1, c2; float c3;
    load_win(x, tile, t, c0, c1, c2, c3);

    for (;;) {
        const int next = tile + NBLOCKS;
        const bool has = (next < NTILES);

        // prefetch next tile's window (loads issue before compute consumes regs)
        float4 q0, q1, q2; float q3;
        if (has) load_win(x, next, t, q0, q1, q2, q3);

        // ---- compute current tile ----
        float p[13];
        p[0]=c0.x;  p[1]=c0.y;  p[2]=c0.z;  p[3]=c0.w;
        p[4]=c1.x;  p[5]=c1.y;  p[6]=c1.z;  p[7]=c1.w;
        p[8]=c2.x;  p[9]=c2.y;  p[10]=c2.z; p[11]=c2.w;
        p[12]=c3;

        u64 E1[5], O1[5], E2[5], R[5], c_[5], m2[5];

        #pragma unroll
        for (int i = 0; i < 5; i++) {
            u64 ppe = pk(p[2*i + 2], p[2*i + 3]);
            u64 ppo = pk(p[2*i + 1], p[2*i + 2]);
            E1[i] = f2fma(ppo, Cm1, ppe);
        }
        const float d1_12 = p[12] - p[11];

        #pragma unroll
        for (int i = 0; i < 4; i++) O1[i] = shifted(E1[i], E1[i + 1]);
        O1[4] = pk(hif(E1[4]), d1_12);

        #pragma unroll
        for (int i = 0; i < 5; i++) {
            E2[i] = f2fma(E1[i], Cm1, O1[i]);
            m2[i] = f2mul(E2[i], E2[i]);
            R[i]  = f2fma(E1[i], E1[i], f2fma(m2[i], C43, Ceps));
            c_[i] = f2mul(E1[i], E2[i]);
        }

        float o[VEC];

        #pragma unroll
        for (int q = 0; q < 4; q++) {
            const int a1 = q, a2 = q + 1;

            const u64 IS0 = f2fma(c_[a1], C3, f2fma(m2[a1], C2, R[a1]));
            const u64 IS2 = f2fma(c_[a2], Cm1, R[a2]);
            const u64 IS1 = f2add(shifted(R[a1], R[a2]), shifted(c_[a1], c_[a2]));

            const u64 T5 = f2abs(f2fma(IS0, Cm1, IS2));

            const u64 t0 = f2add(IS0, T5);
            const u64 t1 = f2add(IS1, T5);
            const u64 t2 = f2add(IS2, T5);
            const u64 g0 = f2mul(Cd0, t0);
            const u64 g1 = f2mul(Cd1, t1);
            const u64 g2 = f2mul(Cd2, t2);
            const u64 e01 = f2mul(IS0, IS1);
            const u64 e02 = f2mul(IS0, IS2);
            const u64 e12 = f2mul(IS1, IS2);
            const u64 w0 = f2mul(g0, e12);
            const u64 w1 = f2mul(g1, e02);
            const u64 w2 = f2mul(g2, e01);

            const u64 X2 = pk(p[2*q + 3], p[2*q + 4]);
            const u64 X3 = pk(p[2*q + 4], p[2*q + 5]);
            const u64 G  = f2fma(O1[a1], C05, X2);
            const u64 P0 = f2fma(E2[a1], C13, G);
            const u64 P1 = f2fma(shifted(E2[a1], E2[a2]), C13, G);
            const u64 P2 = f2fma(E2[a2], Cm16, f2fma(E1[a2], Cm05, X3));

            const u64 num = f2fma(w2, P2, f2fma(w1, P1, f2mul(w0, P0)));
            const u64 den = f2add(f2add(w0, w1), w2);

            float n0f, n1f, d0f, d1f;
            upk(n0f, n1f, num); upk(d0f, d1f, den);
            o[2*q]     = __fdividef(n0f, d0f);
            o[2*q + 1] = __fdividef(n1f, d1f);
        }

        {
            const int bb    = tile >> 10;
            const int start = (tile & 1023) * TILE;
            float* ob = out + ((size_t)bb << 20) + start + t * VEC;
            *reinterpret_cast<float4*>(ob)     = make_float4(o[0], o[1], o[2], o[3]);
            *reinterpret_cast<float4*>(ob + 4) = make_float4(o[4], o[5], o[6], o[7]);
        }

        if (!has) break;
        c0 = q0; c1 = q1; c2 = q2; c3 = q3;
        tile = next;
    }
}

extern "C" void kernel_launch(void* const* d_in, const int* in_sizes, int n_in,
                              void* d_out, int out_size)
{
    const float* x = (const float*)d_in[0];
    float* out = (float*)d_out;
    weno_z_kernel<<<NBLOCKS, TPB>>>(x, out);
}

// round 8
// speedup vs baseline: 1.1568x; 1.1568x over previous
#include <cuda_runtime.h>

// WENO-Z 1-D periodic, B=16 x N=2^20 fp32.
// Stride-4 lane packing: pack outputs (m, m+4) so every packed operand is
// consumed at identical lane alignment -> zero realignment movs.
// Direct aligned LDG.128, packed f32x2 difference-form math. VEC=8.

#define N_ELEMS   1048576
#define N_MASK    (N_ELEMS - 1)
#define TPB       128
#define VEC       8
#define TILE      (TPB * VEC)    // 1024

#define EPS 1e-13f

typedef unsigned long long u64;

__device__ __forceinline__ u64 pk(float lo, float hi) {
    u64 r; asm("mov.b64 %0, {%1, %2};" : "=l"(r) : "f"(lo), "f"(hi)); return r;
}
__device__ __forceinline__ void upk(float& lo, float& hi, u64 v) {
    asm("mov.b64 {%0, %1}, %2;" : "=f"(lo), "=f"(hi) : "l"(v));
}
__device__ __forceinline__ u64 f2mul(u64 a, u64 b) {
    u64 d; asm("mul.rn.f32x2 %0, %1, %2;" : "=l"(d) : "l"(a), "l"(b)); return d;
}
__device__ __forceinline__ u64 f2add(u64 a, u64 b) {
    u64 d; asm("add.rn.f32x2 %0, %1, %2;" : "=l"(d) : "l"(a), "l"(b)); return d;
}
__device__ __forceinline__ u64 f2fma(u64 a, u64 b, u64 c) {
    u64 d; asm("fma.rn.f32x2 %0, %1, %2, %3;" : "=l"(d) : "l"(a), "l"(b), "l"(c)); return d;
}
__device__ __forceinline__ u64 f2abs(u64 a) { return a & 0x7FFFFFFF7FFFFFFFULL; }

__global__ void __launch_bounds__(TPB) weno_z_kernel(
    const float* __restrict__ x, float* __restrict__ out)
{
    const int b     = blockIdx.y;
    const int start = blockIdx.x * TILE;
    const float* xb = x + (size_t)b * N_ELEMS;
    const int t     = threadIdx.x;

    const int n0 = start + t * VEC;      // first output index for this thread
    // p[k] = x[(n0 - 4 + k) & MASK], k = 0..12 ; outputs at p-index m = 4..11
    const int base = n0 - 4;             // multiple of 4 -> 16B-aligned bases
    float4 f0  = *reinterpret_cast<const float4*>(xb + ((base)      & N_MASK));
    float4 f1  = *reinterpret_cast<const float4*>(xb + ((base + 4)  & N_MASK));
    float4 f2v = *reinterpret_cast<const float4*>(xb + ((base + 8)  & N_MASK));
    float p12  = xb[(base + 12) & N_MASK];

    float p[13];
    p[0]=f0.x;  p[1]=f0.y;  p[2]=f0.z;  p[3]=f0.w;
    p[4]=f1.x;  p[5]=f1.y;  p[6]=f1.z;  p[7]=f1.w;
    p[8]=f2v.x; p[9]=f2v.y; p[10]=f2v.z; p[11]=f2v.w;
    p[12]=p12;

    const u64 Cm1  = pk(-1.0f, -1.0f);
    const u64 C2   = pk(2.0f, 2.0f);
    const u64 C3   = pk(3.0f, 3.0f);
    const u64 C43  = pk(4.0f/3.0f, 4.0f/3.0f);
    const u64 C05  = pk(0.5f, 0.5f);
    const u64 Cm05 = pk(-0.5f, -0.5f);
    const u64 C13  = pk(1.0f/3.0f, 1.0f/3.0f);
    const u64 Cm16 = pk(-1.0f/6.0f, -1.0f/6.0f);
    const u64 Ceps = pk(EPS, EPS);
    const u64 Cd0  = pk(0.1f, 0.1f);
    const u64 Cd1  = pk(0.6f, 0.6f);
    const u64 Cd2  = pk(0.3f, 0.3f);

    // PK[i]  = (p[i],  p[i+4]),  i = 1..8
    // PD1[i] = (d1[i], d1[i+4]), i = 2..8   d1[k] = p[k]-p[k-1]
    // PD2[i] = (d2[i], d2[i+4]), i = 2..7   d2[k] = d1[k+1]-d1[k]
    // R[i]   = d1^2 + 4/3 d2^2 + eps ; c[i] = d1*d2 ; S[i] = R + 2 d2^2 (i=2..5)
    u64 PK[9], PD1[9], PD2[8], R[8], c[8], S[6];

    #pragma unroll
    for (int i = 1; i <= 8; i++) PK[i] = pk(p[i], p[i + 4]);

    #pragma unroll
    for (int i = 2; i <= 8; i++) PD1[i] = f2fma(PK[i - 1], Cm1, PK[i]);

    #pragma unroll
    for (int i = 2; i <= 7; i++) {
        PD2[i] = f2fma(PD1[i], Cm1, PD1[i + 1]);
        u64 sq = f2mul(PD2[i], PD2[i]);
        R[i] = f2fma(PD1[i], PD1[i], f2fma(sq, C43, Ceps));
        c[i] = f2mul(PD1[i], PD2[i]);
        if (i <= 5) S[i] = f2fma(sq, C2, R[i]);
    }

    float o[VEC];

    #pragma unroll
    for (int q = 0; q < 4; q++) {
        const int k0 = q + 2, k1 = q + 3, k2 = q + 4;
        // lanes: output m = 4+q (lane0), m+4 = 8+q (lane1) — all operands aligned

        const u64 IS0 = f2fma(c[k0], C3, S[k0]);
        const u64 IS1 = f2add(R[k1], c[k1]);
        const u64 IS2 = f2fma(c[k2], Cm1, R[k2]);

        const u64 T5 = f2abs(f2fma(IS0, Cm1, IS2));

        const u64 t0 = f2add(IS0, T5);
        const u64 t1 = f2add(IS1, T5);
        const u64 t2 = f2add(IS2, T5);
        const u64 g0 = f2mul(Cd0, t0);
        const u64 g1 = f2mul(Cd1, t1);
        const u64 g2 = f2mul(Cd2, t2);
        const u64 e01 = f2mul(IS0, IS1);
        const u64 e02 = f2mul(IS0, IS2);
        const u64 e12 = f2mul(IS1, IS2);
        const u64 w0 = f2mul(g0, e12);
        const u64 w1 = f2mul(g1, e02);
        const u64 w2 = f2mul(g2, e01);

        // G = x2 + d1[m-1]/2 ; P0 = G + d2[m-2]/3 ; P1 = G + d2[m-1]/3
        // P2 = x3 - d1[m]/2 - d2[m]/6
        const u64 G  = f2fma(PD1[k1], C05, PK[k1]);
        const u64 P0 = f2fma(PD2[k0], C13, G);
        const u64 P1 = f2fma(PD2[k1], C13, G);
        const u64 P2 = f2fma(PD2[k2], Cm16, f2fma(PD1[k2], Cm05, PK[k2]));

        const u64 num = f2fma(w2, P2, f2fma(w1, P1, f2mul(w0, P0)));
        const u64 den = f2add(f2add(w0, w1), w2);

        float nlo, nhi, dlo, dhi;
        upk(nlo, nhi, num); upk(dlo, dhi, den);
        o[q]     = __fdividef(nlo, dlo);   // output m   = 4+q
        o[q + 4] = __fdividef(nhi, dhi);   // output m+4 = 8+q
    }

    float* ob = out + (size_t)b * N_ELEMS + n0;
    *reinterpret_cast<float4*>(ob)     = make_float4(o[0], o[1], o[2], o[3]);
    *reinterpret_cast<float4*>(ob + 4) = make_float4(o[4], o[5], o[6], o[7]);
}

extern "C" void kernel_launch(void* const* d_in, const int* in_sizes, int n_in,
                              void* d_out, int out_size)
{
    const float* x = (const float*)d_in[0];
    float* out = (float*)d_out;
    const int total = in_sizes[0];
    const int batches = total / N_ELEMS;

    dim3 grid(N_ELEMS / TILE, batches);
    weno_z_kernel<<<grid, TPB>>>(x, out);
}